// round 12
// baseline (speedup 1.0000x reference)
#include <cuda_runtime.h>

#define DT 0.1f
#define EPSF 1e-6f
#define TPB 256   // 8 warps = 4 warp-pairs; pair p owns agents [A+32p, A+32p+32)

__device__ __forceinline__ float clamp01(float x) {
    return fminf(fmaxf(x, 0.0f), 1.0f);
}

__global__ void __launch_bounds__(TPB, 6) econ_step_kernel(
    const float* __restrict__ need_prev,
    const float* __restrict__ inventory,   // (R, 64)
    const float* __restrict__ endowment,   // (R, 64)
    const float* __restrict__ price,       // (64, R)
    const float* __restrict__ pool_atp,
    const float* __restrict__ pool_adp,
    const float* __restrict__ pool_amp,
    const float* __restrict__ greed,
    const float* __restrict__ innovation,  // (R, 64)
    const float* __restrict__ extraction,  // (R, 32)
    const float* __restrict__ deposits,    // (R, 32)
    const float* __restrict__ exergy_price,
    const float* __restrict__ bases,       // (3,)
    const float* __restrict__ scales,      // (3,)
    float* __restrict__ out,               // [0,R): gdp, [R,2R): aec
    int R)
{
    // Per-pair r-tile: 64 cols x 32 agents, XOR-swizzled.
    __shared__ float s_tile[4 * 64 * 32];   // 32 KB
    __shared__ float s_q[128];              // extraction dot per agent
    __shared__ float s_rate[4 * 32];        // warp-odd partial rate_sum
    __shared__ float s_rp[4 * 32];          // warp-odd partial rp_sum

    const int tid  = threadIdx.x;
    const int lane = tid & 31;
    const int w    = tid >> 5;
    const int p    = w >> 1;                // warp pair (0..3)
    const int h    = w & 1;                 // column half
    const int A    = blockIdx.x * 128;      // 128 agents per block
    const int aw   = A + 32 * p;            // pair's first agent
    const int i    = aw + lane;             // this lane's agent (redundant per pair)

    // ---------------- prologue: per-agent scalars (redundant in pair) ------
    const float adp0     = pool_adp[i];
    const float recharge = fminf(adp0, need_prev[i] * DT);
    const float atp      = pool_atp[i] + recharge;
    const float adp      = adp0 - recharge;
    const float amp      = pool_amp[i];
    const float aec      = (atp + 0.5f * adp) / (atp + adp + amp + EPSF);

    const float g       = greed[i];
    const float innov_f = fminf(fmaxf(bases[1] + scales[1] * g, 0.0f), 0.9f);
    const float stor_f  = fminf(fmaxf(bases[2] + scales[2] * g, 0.0f), 0.9f);

    const float wealth  = atp;
    float atp_book      = wealth - wealth * (innov_f + stor_f);

    const float my_c  = 0.01f * aec;                       // 0.1*DT*aec
    const float my_ib = wealth * innov_f * (1.0f / 64.0f); // innov_budget

    // ---------------- extraction: warp handles agents [16h, 16h+16) --------
    {
        const float4* ex4 = reinterpret_cast<const float4*>(extraction) + (size_t)aw * 8;
        const float4* dp4 = reinterpret_cast<const float4*>(deposits)   + (size_t)aw * 8;
#pragma unroll
        for (int t = 0; t < 4; ++t) {
            const int la  = 16 * h + 4 * t + (lane >> 3);  // local agent
            const int idx = la * 8 + (lane & 7);
            const float4 e = ex4[idx];
            const float4 d = dp4[idx];
            float s = e.x * d.x + e.y * d.y + e.z * d.z + e.w * d.w;
            s += __shfl_xor_sync(0xFFFFFFFFu, s, 1);
            s += __shfl_xor_sync(0xFFFFFFFFu, s, 2);
            s += __shfl_xor_sync(0xFFFFFFFFu, s, 4);
            if ((lane & 7) == 0)
                s_q[32 * p + la] = s;
        }
    }

    // ---------------- production: warp handles cols [32h, 32h+32) ----------
    float* tile = s_tile + p * 2048;
    {
        const float4* inv4 = reinterpret_cast<const float4*>(inventory)  + (size_t)aw * 16 + h * 8;
        const float4* en4  = reinterpret_cast<const float4*>(endowment)  + (size_t)aw * 16 + h * 8;
        const float4* in4  = reinterpret_cast<const float4*>(innovation) + (size_t)aw * 16 + h * 8;

        const int la_of = lane >> 3;            // which of 4 agents this lane
        const int f     = lane & 7;             // float4 index in half-row
        const int col0  = 32 * h + 4 * f;       // first col this lane handles

#pragma unroll 2
        for (int t = 0; t < 8; ++t) {           // 4 agents per iteration
            const int la  = 4 * t + la_of;      // local agent (0..31)
            const int idx = la * 16 + f;
            const float4 inv = inv4[idx];
            const float4 en  = en4[idx];
            const float4 nn  = in4[idx];

            const float c  = __shfl_sync(0xFFFFFFFFu, my_c,  la);
            const float ib = __shfl_sync(0xFFFFFFFFu, my_ib, la);

            const float r0 = c * (nn.x + 0.005f * __fdividef(ib, 1.0f + nn.x)) * fmaxf(inv.x + DT * en.x, 0.0f);
            const float r1 = c * (nn.y + 0.005f * __fdividef(ib, 1.0f + nn.y)) * fmaxf(inv.y + DT * en.y, 0.0f);
            const float r2 = c * (nn.z + 0.005f * __fdividef(ib, 1.0f + nn.z)) * fmaxf(inv.z + DT * en.z, 0.0f);
            const float r3 = c * (nn.w + 0.005f * __fdividef(ib, 1.0f + nn.w)) * fmaxf(inv.w + DT * en.w, 0.0f);

            // tile[col][agent], swizzled: addr = col*32 + ((agent + col) & 31)
            tile[(col0 + 0) * 32 + ((la + col0 + 0) & 31)] = r0;
            tile[(col0 + 1) * 32 + ((la + col0 + 1) & 31)] = r1;
            tile[(col0 + 2) * 32 + ((la + col0 + 2) & 31)] = r2;
            tile[(col0 + 3) * 32 + ((la + col0 + 3) & 31)] = r3;
        }
    }
    __syncwarp();   // tile cols [32h,32h+32) written entirely by this warp

    // ---------------- per-warp partial sums over own 32 cols ---------------
    // lane = agent; cols [32h, 32h+32); price loads coalesced across lanes.
    float rate_p = 0.0f;
    float rp_p   = 0.0f;
    {
        const float* pcol = price + (size_t)(32 * h) * R + i;
#pragma unroll 8
        for (int k = 0; k < 32; ++k) {
            const int col = 32 * h + k;
            const float r  = tile[col * 32 + ((lane + col) & 31)];
            const float pr = pcol[(size_t)k * R];
            rate_p += r;
            rp_p   += r * pr;
        }
    }

    if (h == 1) {
        s_rate[32 * p + lane] = rate_p;
        s_rp[32 * p + lane]   = rp_p;
    }
    __syncthreads();   // the only block-wide barrier

    // ---------------- finale: warp-even combines + epilogue ----------------
    if (h == 0) {
        const float rate_sum = rate_p + s_rate[32 * p + lane];
        const float rp_sum   = rp_p   + s_rp[32 * p + lane];

        float qsum = s_q[32 * p + lane] * DT;
        const float cost  = qsum * 0.5f;
        const float scale = clamp01(atp_book / (cost + EPSF));
        const float q_scaled_sum = qsum * scale;
        atp_book -= scale * cost;

        const float pcost  = rate_sum * 0.3f;
        const float pscale = clamp01(atp_book / (pcost + EPSF));

        float ep = exergy_price[i] * (1.0f + 0.02f * (0.5f - aec));
        ep = fminf(fmaxf(ep, 1e-4f), 1e4f);

        out[i]     = pscale * rp_sum + q_scaled_sum * ep;
        out[R + i] = aec;
    }
}

extern "C" void kernel_launch(void* const* d_in, const int* in_sizes, int n_in,
                              void* d_out, int out_size) {
    const float* need_prev    = (const float*)d_in[0];
    const float* inventory    = (const float*)d_in[1];
    const float* endowment    = (const float*)d_in[2];
    const float* price        = (const float*)d_in[3];
    const float* pool_atp     = (const float*)d_in[4];
    const float* pool_adp     = (const float*)d_in[5];
    const float* pool_amp     = (const float*)d_in[6];
    const float* greed        = (const float*)d_in[8];
    const float* innovation   = (const float*)d_in[9];
    const float* extraction   = (const float*)d_in[10];
    const float* deposits     = (const float*)d_in[11];
    const float* exergy_price = (const float*)d_in[15];
    const float* bases        = (const float*)d_in[17];
    const float* scales       = (const float*)d_in[18];
    float* out = (float*)d_out;

    const int R = in_sizes[0];       // 131072; 128 agents per block
    const int blocks = R / 128;
    econ_step_kernel<<<blocks, TPB>>>(
        need_prev, inventory, endowment, price,
        pool_atp, pool_adp, pool_amp, greed,
        innovation, extraction, deposits, exergy_price,
        bases, scales, out, R);
}

// round 13
// speedup vs baseline: 1.1467x; 1.1467x over previous
#include <cuda_runtime.h>

#define DT 0.1f
#define EPSF 1e-6f
#define TPB 256   // 8 warps = 4 warp-pairs; pair p owns agents [A+32p, A+32p+32)

__device__ __forceinline__ float clamp01(float x) {
    return fminf(fmaxf(x, 0.0f), 1.0f);
}

__global__ void __launch_bounds__(TPB, 5) econ_step_kernel(
    const float* __restrict__ need_prev,
    const float* __restrict__ inventory,   // (R, 64)
    const float* __restrict__ endowment,   // (R, 64)
    const float* __restrict__ price,       // (64, R)
    const float* __restrict__ pool_atp,
    const float* __restrict__ pool_adp,
    const float* __restrict__ pool_amp,
    const float* __restrict__ greed,
    const float* __restrict__ innovation,  // (R, 64)
    const float* __restrict__ extraction,  // (R, 32)
    const float* __restrict__ deposits,    // (R, 32)
    const float* __restrict__ exergy_price,
    const float* __restrict__ bases,       // (3,)
    const float* __restrict__ scales,      // (3,)
    float* __restrict__ out,               // [0,R): gdp, [R,2R): aec
    int R)
{
    // Per-pair r-tile: 64 cols x 32 agents, XOR-swizzled.
    __shared__ float s_tile[4 * 64 * 32];   // 32 KB
    __shared__ float s_q[128];              // extraction dot per agent
    __shared__ float s_rate[4 * 32];        // warp-odd partial rate_sum
    __shared__ float s_rp[4 * 32];          // warp-odd partial rp_sum

    const int tid  = threadIdx.x;
    const int lane = tid & 31;
    const int w    = tid >> 5;
    const int p    = w >> 1;                // warp pair (0..3)
    const int h    = w & 1;                 // column half
    const int A    = blockIdx.x * 128;      // 128 agents per block
    const int aw   = A + 32 * p;            // pair's first agent
    const int i    = aw + lane;             // this lane's agent (redundant per pair)

    // ---------------- prologue: per-agent scalars (redundant in pair) ------
    const float adp0     = pool_adp[i];
    const float recharge = fminf(adp0, need_prev[i] * DT);
    const float atp      = pool_atp[i] + recharge;
    const float adp      = adp0 - recharge;
    const float amp      = pool_amp[i];
    const float aec      = (atp + 0.5f * adp) / (atp + adp + amp + EPSF);

    const float g       = greed[i];
    const float innov_f = fminf(fmaxf(bases[1] + scales[1] * g, 0.0f), 0.9f);
    const float stor_f  = fminf(fmaxf(bases[2] + scales[2] * g, 0.0f), 0.9f);

    const float wealth  = atp;
    float atp_book      = wealth - wealth * (innov_f + stor_f);

    const float my_c  = 0.01f * aec;                       // 0.1*DT*aec
    const float my_ib = wealth * innov_f * (1.0f / 64.0f); // innov_budget

    // ---------------- extraction: warp handles agents [16h, 16h+16) --------
    // Pass 1: issue all 8 LDG.128 and fold to scalar dots (no cross-lane deps
    // between loads -> 8 loads in flight). Pass 2: shuffle reductions.
    float sdot[4];
    {
        const float4* ex4 = reinterpret_cast<const float4*>(extraction) + (size_t)aw * 8;
        const float4* dp4 = reinterpret_cast<const float4*>(deposits)   + (size_t)aw * 8;
#pragma unroll
        for (int t = 0; t < 4; ++t) {
            const int la  = 16 * h + 4 * t + (lane >> 3);  // local agent
            const int idx = la * 8 + (lane & 7);
            const float4 e = ex4[idx];
            const float4 d = dp4[idx];
            sdot[t] = e.x * d.x + e.y * d.y + e.z * d.z + e.w * d.w;
        }
#pragma unroll
        for (int t = 0; t < 4; ++t) {
            float s = sdot[t];
            s += __shfl_xor_sync(0xFFFFFFFFu, s, 1);
            s += __shfl_xor_sync(0xFFFFFFFFu, s, 2);
            s += __shfl_xor_sync(0xFFFFFFFFu, s, 4);
            if ((lane & 7) == 0)
                s_q[32 * p + 16 * h + 4 * t + (lane >> 3)] = s;
        }
    }

    // ---------------- production: warp handles cols [32h, 32h+32) ----------
    float* tile = s_tile + p * 2048;
    {
        const float4* inv4 = reinterpret_cast<const float4*>(inventory)  + (size_t)aw * 16 + h * 8;
        const float4* en4  = reinterpret_cast<const float4*>(endowment)  + (size_t)aw * 16 + h * 8;
        const float4* in4  = reinterpret_cast<const float4*>(innovation) + (size_t)aw * 16 + h * 8;

        const int la_of = lane >> 3;            // which of 4 agents this lane
        const int f     = lane & 7;             // float4 index in half-row
        const int col0  = 32 * h + 4 * f;       // first col this lane handles

#pragma unroll 4
        for (int t = 0; t < 8; ++t) {           // 4 agents per iteration
            const int la  = 4 * t + la_of;      // local agent (0..31)
            const int idx = la * 16 + f;
            const float4 inv = inv4[idx];
            const float4 en  = en4[idx];
            const float4 nn  = in4[idx];

            const float c  = __shfl_sync(0xFFFFFFFFu, my_c,  la);
            const float ib = __shfl_sync(0xFFFFFFFFu, my_ib, la);

            const float r0 = c * (nn.x + 0.005f * __fdividef(ib, 1.0f + nn.x)) * fmaxf(inv.x + DT * en.x, 0.0f);
            const float r1 = c * (nn.y + 0.005f * __fdividef(ib, 1.0f + nn.y)) * fmaxf(inv.y + DT * en.y, 0.0f);
            const float r2 = c * (nn.z + 0.005f * __fdividef(ib, 1.0f + nn.z)) * fmaxf(inv.z + DT * en.z, 0.0f);
            const float r3 = c * (nn.w + 0.005f * __fdividef(ib, 1.0f + nn.w)) * fmaxf(inv.w + DT * en.w, 0.0f);

            // tile[col][agent], swizzled: addr = col*32 + ((agent + col) & 31)
            tile[(col0 + 0) * 32 + ((la + col0 + 0) & 31)] = r0;
            tile[(col0 + 1) * 32 + ((la + col0 + 1) & 31)] = r1;
            tile[(col0 + 2) * 32 + ((la + col0 + 2) & 31)] = r2;
            tile[(col0 + 3) * 32 + ((la + col0 + 3) & 31)] = r3;
        }
    }
    __syncwarp();   // tile cols [32h,32h+32) written entirely by this warp

    // ---------------- per-warp partial sums over own 32 cols ---------------
    // lane = agent; cols [32h, 32h+32); price loads coalesced across lanes.
    float rate_p = 0.0f;
    float rp_p   = 0.0f;
    {
        const float* pcol = price + (size_t)(32 * h) * R + i;
#pragma unroll 8
        for (int k = 0; k < 32; ++k) {
            const int col = 32 * h + k;
            const float r  = tile[col * 32 + ((lane + col) & 31)];
            const float pr = pcol[(size_t)k * R];
            rate_p += r;
            rp_p   += r * pr;
        }
    }

    if (h == 1) {
        s_rate[32 * p + lane] = rate_p;
        s_rp[32 * p + lane]   = rp_p;
    }
    __syncthreads();   // the only block-wide barrier

    // ---------------- finale: warp-even combines + epilogue ----------------
    if (h == 0) {
        const float rate_sum = rate_p + s_rate[32 * p + lane];
        const float rp_sum   = rp_p   + s_rp[32 * p + lane];

        float qsum = s_q[32 * p + lane] * DT;
        const float cost  = qsum * 0.5f;
        const float scale = clamp01(atp_book / (cost + EPSF));
        const float q_scaled_sum = qsum * scale;
        atp_book -= scale * cost;

        const float pcost  = rate_sum * 0.3f;
        const float pscale = clamp01(atp_book / (pcost + EPSF));

        float ep = exergy_price[i] * (1.0f + 0.02f * (0.5f - aec));
        ep = fminf(fmaxf(ep, 1e-4f), 1e4f);

        out[i]     = pscale * rp_sum + q_scaled_sum * ep;
        out[R + i] = aec;
    }
}

extern "C" void kernel_launch(void* const* d_in, const int* in_sizes, int n_in,
                              void* d_out, int out_size) {
    const float* need_prev    = (const float*)d_in[0];
    const float* inventory    = (const float*)d_in[1];
    const float* endowment    = (const float*)d_in[2];
    const float* price        = (const float*)d_in[3];
    const float* pool_atp     = (const float*)d_in[4];
    const float* pool_adp     = (const float*)d_in[5];
    const float* pool_amp     = (const float*)d_in[6];
    const float* greed        = (const float*)d_in[8];
    const float* innovation   = (const float*)d_in[9];
    const float* extraction   = (const float*)d_in[10];
    const float* deposits     = (const float*)d_in[11];
    const float* exergy_price = (const float*)d_in[15];
    const float* bases        = (const float*)d_in[17];
    const float* scales       = (const float*)d_in[18];
    float* out = (float*)d_out;

    const int R = in_sizes[0];       // 131072; 128 agents per block
    const int blocks = R / 128;
    econ_step_kernel<<<blocks, TPB>>>(
        need_prev, inventory, endowment, price,
        pool_atp, pool_adp, pool_amp, greed,
        innovation, extraction, deposits, exergy_price,
        bases, scales, out, R);
}

// round 14
// speedup vs baseline: 1.1487x; 1.0017x over previous
#include <cuda_runtime.h>

#define DT 0.1f
#define EPSF 1e-6f
#define TPB 256   // 8 warps = 4 warp-pairs; pair p owns agents [A+32p, A+32p+32)

__device__ __forceinline__ float clamp01(float x) {
    return fminf(fmaxf(x, 0.0f), 1.0f);
}

__global__ void __launch_bounds__(TPB, 5) econ_step_kernel(
    const float* __restrict__ need_prev,
    const float* __restrict__ inventory,   // (R, 64)
    const float* __restrict__ endowment,   // (R, 64)
    const float* __restrict__ price,       // (64, R)
    const float* __restrict__ pool_atp,
    const float* __restrict__ pool_adp,
    const float* __restrict__ pool_amp,
    const float* __restrict__ greed,
    const float* __restrict__ innovation,  // (R, 64)
    const float* __restrict__ extraction,  // (R, 32)
    const float* __restrict__ deposits,    // (R, 32)
    const float* __restrict__ exergy_price,
    const float* __restrict__ bases,       // (3,)
    const float* __restrict__ scales,      // (3,)
    float* __restrict__ out,               // [0,R): gdp, [R,2R): aec
    int R)
{
    // Per-pair price tile: 64 cols x 32 agents, stride 33 (conflict-free
    // for per-col STS (bank=lane+c) and for production LDS (banks 4f+la_of)).
    __shared__ float s_price[4 * 64 * 33];  // 33 KB
    __shared__ float s_q[128];              // extraction dot per agent
    __shared__ float s_rate[2 * 128];       // per-half per-agent rate partials
    __shared__ float s_rp[2 * 128];         // per-half per-agent r*p partials

    const int tid  = threadIdx.x;
    const int lane = tid & 31;
    const int w    = tid >> 5;
    const int p    = w >> 1;                // warp pair (0..3)
    const int h    = w & 1;                 // column half
    const int A    = blockIdx.x * 128;      // 128 agents per block
    const int aw   = A + 32 * p;            // pair's first agent
    const int i    = aw + lane;             // this lane's agent (redundant per pair)

    // ---------------- phase 1: price tile (32 coalesced, independent LDG) --
    float* ps = s_price + p * (64 * 33);
    {
        const float* pg = price + (size_t)(32 * h) * R + aw + lane;
#pragma unroll 8
        for (int k = 0; k < 32; ++k) {
            ps[(32 * h + k) * 33 + lane] = pg[(size_t)k * R];
        }
    }

    // ---------------- prologue: per-agent scalars (redundant in pair) ------
    const float adp0     = pool_adp[i];
    const float recharge = fminf(adp0, need_prev[i] * DT);
    const float atp      = pool_atp[i] + recharge;
    const float adp      = adp0 - recharge;
    const float amp      = pool_amp[i];
    const float aec      = (atp + 0.5f * adp) / (atp + adp + amp + EPSF);

    const float g       = greed[i];
    const float innov_f = fminf(fmaxf(bases[1] + scales[1] * g, 0.0f), 0.9f);
    const float stor_f  = fminf(fmaxf(bases[2] + scales[2] * g, 0.0f), 0.9f);

    const float wealth  = atp;
    float atp_book      = wealth - wealth * (innov_f + stor_f);

    const float my_c  = 0.01f * aec;                       // 0.1*DT*aec
    const float my_ib = wealth * innov_f * (1.0f / 64.0f); // innov_budget

    // ---------------- extraction: warp handles agents [16h, 16h+16) --------
    {
        const float4* ex4 = reinterpret_cast<const float4*>(extraction) + (size_t)aw * 8;
        const float4* dp4 = reinterpret_cast<const float4*>(deposits)   + (size_t)aw * 8;
        float sdot[4];
#pragma unroll
        for (int t = 0; t < 4; ++t) {
            const int la  = 16 * h + 4 * t + (lane >> 3);  // local agent
            const int idx = la * 8 + (lane & 7);
            const float4 e = ex4[idx];
            const float4 d = dp4[idx];
            sdot[t] = e.x * d.x + e.y * d.y + e.z * d.z + e.w * d.w;
        }
#pragma unroll
        for (int t = 0; t < 4; ++t) {
            float s = sdot[t];
            s += __shfl_xor_sync(0xFFFFFFFFu, s, 1);
            s += __shfl_xor_sync(0xFFFFFFFFu, s, 2);
            s += __shfl_xor_sync(0xFFFFFFFFu, s, 4);
            if ((lane & 7) == 0)
                s_q[32 * p + 16 * h + 4 * t + (lane >> 3)] = s;
        }
    }

    __syncwarp();   // price STS visible to warp-mates before production LDS

    // ---------------- production: fused compute + price dot ----------------
    {
        const float4* inv4 = reinterpret_cast<const float4*>(inventory)  + (size_t)aw * 16 + h * 8;
        const float4* en4  = reinterpret_cast<const float4*>(endowment)  + (size_t)aw * 16 + h * 8;
        const float4* in4  = reinterpret_cast<const float4*>(innovation) + (size_t)aw * 16 + h * 8;

        const int la_of = lane >> 3;            // which of 4 agents this lane
        const int f     = lane & 7;             // float4 index in half-row
        const int col0  = 32 * h + 4 * f;       // first col this lane handles

#pragma unroll 4
        for (int t = 0; t < 8; ++t) {           // 4 agents per iteration
            const int la  = 4 * t + la_of;      // local agent (0..31)
            const int idx = la * 16 + f;
            const float4 inv = inv4[idx];
            const float4 en  = en4[idx];
            const float4 nn  = in4[idx];

            const float c  = __shfl_sync(0xFFFFFFFFu, my_c,  la);
            const float ib = __shfl_sync(0xFFFFFFFFu, my_ib, la);

            const float r0 = c * (nn.x + 0.005f * __fdividef(ib, 1.0f + nn.x)) * fmaxf(inv.x + DT * en.x, 0.0f);
            const float r1 = c * (nn.y + 0.005f * __fdividef(ib, 1.0f + nn.y)) * fmaxf(inv.y + DT * en.y, 0.0f);
            const float r2 = c * (nn.z + 0.005f * __fdividef(ib, 1.0f + nn.z)) * fmaxf(inv.z + DT * en.z, 0.0f);
            const float r3 = c * (nn.w + 0.005f * __fdividef(ib, 1.0f + nn.w)) * fmaxf(inv.w + DT * en.w, 0.0f);

            const float p0 = ps[(col0 + 0) * 33 + la];
            const float p1 = ps[(col0 + 1) * 33 + la];
            const float p2 = ps[(col0 + 2) * 33 + la];
            const float p3 = ps[(col0 + 3) * 33 + la];

            float rl = (r0 + r1) + (r2 + r3);
            float pl = (r0 * p0 + r1 * p1) + (r2 * p2 + r3 * p3);
            rl += __shfl_xor_sync(0xFFFFFFFFu, rl, 1);
            pl += __shfl_xor_sync(0xFFFFFFFFu, pl, 1);
            rl += __shfl_xor_sync(0xFFFFFFFFu, rl, 2);
            pl += __shfl_xor_sync(0xFFFFFFFFu, pl, 2);
            rl += __shfl_xor_sync(0xFFFFFFFFu, rl, 4);
            pl += __shfl_xor_sync(0xFFFFFFFFu, pl, 4);
            if (f == 0) {
                s_rate[h * 128 + 32 * p + la] = rl;
                s_rp[h * 128 + 32 * p + la]   = pl;
            }
        }
    }

    // ---------------- per-pair named barrier (pairs decoupled) -------------
    asm volatile("bar.sync %0, %1;" :: "r"(1 + p), "r"(64) : "memory");

    // ---------------- finale: warp-even combines + epilogue ----------------
    if (h == 0) {
        const float rate_sum = s_rate[32 * p + lane] + s_rate[128 + 32 * p + lane];
        const float rp_sum   = s_rp[32 * p + lane]   + s_rp[128 + 32 * p + lane];

        float qsum = s_q[32 * p + lane] * DT;
        const float cost  = qsum * 0.5f;
        const float scale = clamp01(atp_book / (cost + EPSF));
        const float q_scaled_sum = qsum * scale;
        atp_book -= scale * cost;

        const float pcost  = rate_sum * 0.3f;
        const float pscale = clamp01(atp_book / (pcost + EPSF));

        float ep = exergy_price[i] * (1.0f + 0.02f * (0.5f - aec));
        ep = fminf(fmaxf(ep, 1e-4f), 1e4f);

        out[i]     = pscale * rp_sum + q_scaled_sum * ep;
        out[R + i] = aec;
    }
}

extern "C" void kernel_launch(void* const* d_in, const int* in_sizes, int n_in,
                              void* d_out, int out_size) {
    const float* need_prev    = (const float*)d_in[0];
    const float* inventory    = (const float*)d_in[1];
    const float* endowment    = (const float*)d_in[2];
    const float* price        = (const float*)d_in[3];
    const float* pool_atp     = (const float*)d_in[4];
    const float* pool_adp     = (const float*)d_in[5];
    const float* pool_amp     = (const float*)d_in[6];
    const float* greed        = (const float*)d_in[8];
    const float* innovation   = (const float*)d_in[9];
    const float* extraction   = (const float*)d_in[10];
    const float* deposits     = (const float*)d_in[11];
    const float* exergy_price = (const float*)d_in[15];
    const float* bases        = (const float*)d_in[17];
    const float* scales       = (const float*)d_in[18];
    float* out = (float*)d_out;

    const int R = in_sizes[0];       // 131072; 128 agents per block
    const int blocks = R / 128;
    econ_step_kernel<<<blocks, TPB>>>(
        need_prev, inventory, endowment, price,
        pool_atp, pool_adp, pool_amp, greed,
        innovation, extraction, deposits, exergy_price,
        bases, scales, out, R);
}